// round 2
// baseline (speedup 1.0000x reference)
#include <cuda_runtime.h>
#include <cstdint>

#define BN      131072          // B*N
#define NPROP   16384
#define BIMG    8
#define M_ENT   32768           // N*(C-1)
#define NEGF    (-1e9f)
#define HALF_NEG (-5e8f)
#define NMS_ITERS 640
#define DET     320
#define BBOX_CLIP_F 4.135166556742356f

// scratch (static device globals; no allocation allowed)
__device__ float4 g_nbox[BIMG * M_ENT];   // offset boxes for IoU
__device__ float4 g_box [BIMG * M_ENT];   // clipped boxes for output
__device__ float  g_s0  [BIMG * M_ENT];   // initial masked scores

// ---------------------------------------------------------------------------
// Prep: decode + softmax + clip + validity, per proposal (2 classes each)
// ---------------------------------------------------------------------------
__global__ void prep_kernel(const float* __restrict__ logits,
                            const float* __restrict__ breg,
                            const float* __restrict__ props)
{
    int g = blockIdx.x * blockDim.x + threadIdx.x;
    if (g >= BN) return;
    int b = g >> 14;            // / 16384
    int n = g & (NPROP - 1);

    // softmax over 3 classes
    float l0 = logits[g * 3 + 0];
    float l1 = logits[g * 3 + 1];
    float l2 = logits[g * 3 + 2];
    float mx = fmaxf(l0, fmaxf(l1, l2));
    float e0 = expf(l0 - mx), e1 = expf(l1 - mx), e2 = expf(l2 - mx);
    float sum = e0 + e1 + e2;
    float sc[2] = { e1 / sum, e2 / sum };

    float px1 = props[g * 4 + 0];
    float py1 = props[g * 4 + 1];
    float px2 = props[g * 4 + 2];
    float py2 = props[g * 4 + 3];
    float w  = px2 - px1;
    float h  = py2 - py1;
    float cx = px1 + 0.5f * w;
    float cy = py1 + 0.5f * h;

    const float fs = 1024.0f;

    #pragma unroll
    for (int c = 1; c <= 2; c++) {
        float r0 = breg[g * 12 + 4 * c + 0];
        float r1 = breg[g * 12 + 4 * c + 1];
        float r2 = breg[g * 12 + 4 * c + 2];
        float r3 = breg[g * 12 + 4 * c + 3];
        float dx = r0 / 10.0f;
        float dy = r1 / 10.0f;
        float dw = fminf(r2 / 5.0f, BBOX_CLIP_F);
        float dh = fminf(r3 / 5.0f, BBOX_CLIP_F);
        float pcx = dx * w + cx;
        float pcy = dy * h + cy;
        float pw = expf(dw) * w;
        float ph = expf(dh) * h;
        float x1 = pcx - 0.5f * pw;
        float y1 = pcy - 0.5f * ph;
        float x2 = pcx + 0.5f * pw;
        float y2 = pcy + 0.5f * ph;
        // clip to image
        x1 = fminf(fmaxf(x1, 0.0f), fs);
        y1 = fminf(fmaxf(y1, 0.0f), fs);
        x2 = fminf(fmaxf(x2, 0.0f), fs);
        y2 = fminf(fmaxf(y2, 0.0f), fs);

        float s = sc[c - 1];
        bool valid = (s > 0.3f) && ((x2 - x1) >= 0.01f) && ((y2 - y1) >= 0.01f);

        float off = (float)c * (fs + 1.0f);   // 1025 or 2050 (exact)
        int m = 2 * n + (c - 1);
        int o = b * M_ENT + m;
        g_box[o]  = make_float4(x1, y1, x2, y2);
        g_nbox[o] = make_float4(x1 + off, y1 + off, x2 + off, y2 + off);
        g_s0[o]   = valid ? s : NEGF;
    }
}

// ---------------------------------------------------------------------------
// NMS: one block per image, persistent. Scores in registers (32/thread),
// strided ownership j = e*1024 + t for coalesced box loads.
// ---------------------------------------------------------------------------
__device__ __forceinline__ unsigned long long pack_key(float s, unsigned j)
{
    unsigned fb = __float_as_uint(s);
    fb = (fb & 0x80000000u) ? ~fb : (fb | 0x80000000u);   // sortable float
    return ((unsigned long long)fb << 32) | (unsigned long long)(0xFFFFFFFFu - j);
}

__global__ void __launch_bounds__(1024, 1)
nms_kernel(float* __restrict__ out)
{
    __shared__ unsigned long long warpRed[32];
    __shared__ unsigned long long bcastKey;
    __shared__ unsigned int recIdx[NMS_ITERS];
    __shared__ float         recScore[NMS_ITERS];
    __shared__ int           slots[NMS_ITERS];

    const int t = threadIdx.x;
    const int b = blockIdx.x;
    const int base = b * M_ENT;

    float s[32];
    #pragma unroll
    for (int e = 0; e < 32; e++)
        s[e] = g_s0[base + e * 1024 + t];

    bool dirty = true;
    unsigned long long lmax = 0ull;

    for (int it = 0; it < NMS_ITERS; ++it) {
        if (dirty) {
            lmax = 0ull;
            #pragma unroll
            for (int e = 0; e < 32; e++) {
                unsigned long long k = pack_key(s[e], (unsigned)(e * 1024 + t));
                lmax = (k > lmax) ? k : lmax;
            }
            dirty = false;
        }
        unsigned long long k = lmax;
        #pragma unroll
        for (int o = 16; o > 0; o >>= 1) {
            unsigned long long other = __shfl_down_sync(0xffffffffu, k, o);
            k = (other > k) ? other : k;
        }
        if ((t & 31) == 0) warpRed[t >> 5] = k;
        __syncthreads();
        if (t < 32) {
            k = warpRed[t];
            #pragma unroll
            for (int o = 16; o > 0; o >>= 1) {
                unsigned long long other = __shfl_down_sync(0xffffffffu, k, o);
                k = (other > k) ? other : k;
            }
            if (t == 0) bcastKey = k;
        }
        __syncthreads();
        k = bcastKey;
        unsigned fb = (unsigned)(k >> 32);
        unsigned orig = (fb & 0x80000000u) ? (fb ^ 0x80000000u) : ~fb;
        float si = __uint_as_float(orig);
        unsigned i = 0xFFFFFFFFu - (unsigned)(k & 0xFFFFFFFFu);

        if (t == 0) { recIdx[it] = i; recScore[it] = si; }

        // selected (offset) box — same address across warp, broadcast load
        float4 nb = g_nbox[base + i];
        float a1 = (nb.z - nb.x) * (nb.w - nb.y);

        #pragma unroll
        for (int e = 0; e < 32; e++) {
            if (s[e] > HALF_NEG) {
                int j = e * 1024 + t;
                float4 c = g_nbox[base + j];
                float ltx = fmaxf(nb.x, c.x);
                float lty = fmaxf(nb.y, c.y);
                float rbx = fminf(nb.z, c.z);
                float rby = fminf(nb.w, c.w);
                float iw = fmaxf(rbx - ltx, 0.0f);
                float ih = fmaxf(rby - lty, 0.0f);
                float inter = iw * ih;
                float a2 = (c.z - c.x) * (c.w - c.y);
                float iou = inter / (a1 + a2 - inter);
                if (iou > 0.3f || (unsigned)j == i) { s[e] = NEGF; dirty = true; }
            }
        }
        // no barrier needed here: warpRed rewritten only after next __syncthreads
    }

    // ------------------- epilogue: stable prio reorder + write -------------
    __syncthreads();

    float* oBoxes  = out;                         // [8][320][4]
    float* oScores = out + BIMG * DET * 4;        // [8][320]
    float* oLabels = out + BIMG * DET * 5;        // [8][320]

    for (int q = t; q < DET * 4; q += 1024) oBoxes[b * DET * 4 + q] = 0.0f;
    for (int q = t; q < DET;     q += 1024) { oScores[b * DET + q] = 0.0f; oLabels[b * DET + q] = 0.0f; }

    if (t == 0) {
        int c0 = 0;
        for (int r = 0; r < NMS_ITERS; r++)
            if (recScore[r] > HALF_NEG && (recIdx[r] & 1u)) c0++;
        int p0 = 0, p1 = 0;
        for (int r = 0; r < NMS_ITERS; r++) {
            bool ok = recScore[r] > HALF_NEG;
            int slot = -1;
            if (ok) slot = (recIdx[r] & 1u) ? (p0++) : (c0 + p1++);
            slots[r] = slot;
        }
    }
    __syncthreads();

    if (t < NMS_ITERS) {
        int slot = slots[t];
        if (slot >= 0 && slot < DET) {
            unsigned i = recIdx[t];
            float4 bx = g_box[base + i];
            float* dst = oBoxes + (b * DET + slot) * 4;
            dst[0] = bx.x; dst[1] = bx.y; dst[2] = bx.z; dst[3] = bx.w;
            oScores[b * DET + slot] = recScore[t];
            oLabels[b * DET + slot] = (float)((i & 1u) + 1u);
        }
    }
}

// ---------------------------------------------------------------------------
extern "C" void kernel_launch(void* const* d_in, const int* in_sizes, int n_in,
                              void* d_out, int out_size)
{
    (void)in_sizes; (void)n_in; (void)out_size;
    const float* logits = (const float*)d_in[0];
    const float* breg   = (const float*)d_in[1];
    const float* props  = (const float*)d_in[2];
    float* out = (float*)d_out;

    prep_kernel<<<(BN + 255) / 256, 256>>>(logits, breg, props);
    nms_kernel<<<BIMG, 1024>>>(out);
}

// round 3
// speedup vs baseline: 8.5802x; 8.5802x over previous
#include <cuda_runtime.h>
#include <cstdint>

#define BN      131072          // B*N
#define NPROP   16384
#define BIMG    8
#define M_ENT   32768           // N*(C-1)
#define CLU     8               // CTAs per image (cluster size)
#define PER_CTA 4096            // entries per CTA
#define PER_THR 4               // entries per thread
#define NEGF    (-1e9f)
#define HALF_NEG (-5e8f)
#define NMS_ITERS 640
#define DET     320
#define BBOX_CLIP_F 4.135166556742356f

typedef unsigned long long u64;

// scratch (static device globals; no allocation allowed)
__device__ float4 g_nbox[BIMG * M_ENT];   // offset boxes for IoU
__device__ float4 g_box [BIMG * M_ENT];   // clipped boxes for output
__device__ float  g_s0  [BIMG * M_ENT];   // initial masked scores

// ---------------------------------------------------------------------------
// Prep: decode + softmax + clip + validity, per proposal (2 classes each)
// ---------------------------------------------------------------------------
__global__ void prep_kernel(const float* __restrict__ logits,
                            const float* __restrict__ breg,
                            const float* __restrict__ props)
{
    int g = blockIdx.x * blockDim.x + threadIdx.x;
    if (g >= BN) return;
    int b = g >> 14;            // / 16384
    int n = g & (NPROP - 1);

    float l0 = logits[g * 3 + 0];
    float l1 = logits[g * 3 + 1];
    float l2 = logits[g * 3 + 2];
    float mx = fmaxf(l0, fmaxf(l1, l2));
    float e0 = expf(l0 - mx), e1 = expf(l1 - mx), e2 = expf(l2 - mx);
    float sum = e0 + e1 + e2;
    float sc[2] = { e1 / sum, e2 / sum };

    float px1 = props[g * 4 + 0];
    float py1 = props[g * 4 + 1];
    float px2 = props[g * 4 + 2];
    float py2 = props[g * 4 + 3];
    float w  = px2 - px1;
    float h  = py2 - py1;
    float cx = px1 + 0.5f * w;
    float cy = py1 + 0.5f * h;

    const float fs = 1024.0f;

    #pragma unroll
    for (int c = 1; c <= 2; c++) {
        float r0 = breg[g * 12 + 4 * c + 0];
        float r1 = breg[g * 12 + 4 * c + 1];
        float r2 = breg[g * 12 + 4 * c + 2];
        float r3 = breg[g * 12 + 4 * c + 3];
        float dx = r0 / 10.0f;
        float dy = r1 / 10.0f;
        float dw = fminf(r2 / 5.0f, BBOX_CLIP_F);
        float dh = fminf(r3 / 5.0f, BBOX_CLIP_F);
        float pcx = dx * w + cx;
        float pcy = dy * h + cy;
        float pw = expf(dw) * w;
        float ph = expf(dh) * h;
        float x1 = pcx - 0.5f * pw;
        float y1 = pcy - 0.5f * ph;
        float x2 = pcx + 0.5f * pw;
        float y2 = pcy + 0.5f * ph;
        x1 = fminf(fmaxf(x1, 0.0f), fs);
        y1 = fminf(fmaxf(y1, 0.0f), fs);
        x2 = fminf(fmaxf(x2, 0.0f), fs);
        y2 = fminf(fmaxf(y2, 0.0f), fs);

        float s = sc[c - 1];
        bool valid = (s > 0.3f) && ((x2 - x1) >= 0.01f) && ((y2 - y1) >= 0.01f);

        float off = (float)c * (fs + 1.0f);   // 1025 or 2050 (exact)
        int m = 2 * n + (c - 1);
        int o = b * M_ENT + m;
        g_box[o]  = make_float4(x1, y1, x2, y2);
        g_nbox[o] = make_float4(x1 + off, y1 + off, x2 + off, y2 + off);
        g_s0[o]   = valid ? s : NEGF;
    }
}

// ---------------------------------------------------------------------------
// helpers
// ---------------------------------------------------------------------------
__device__ __forceinline__ uint32_t smem_u32(const void* p)
{
    uint32_t a;
    asm("{ .reg .u64 t; cvta.to.shared.u64 t, %1; cvt.u32.u64 %0, t; }"
        : "=r"(a) : "l"(p));
    return a;
}

__device__ __forceinline__ void st_cluster64(uint32_t laddr, uint32_t rank, u64 v)
{
    uint32_t r;
    asm volatile("mapa.shared::cluster.u32 %0, %1, %2;" : "=r"(r) : "r"(laddr), "r"(rank));
    asm volatile("st.shared::cluster.b64 [%0], %1;" :: "r"(r), "l"(v) : "memory");
}

__device__ __forceinline__ u64 pack_key(float s, unsigned j)
{
    unsigned fb = __float_as_uint(s);
    fb = (fb & 0x80000000u) ? ~fb : (fb | 0x80000000u);   // sortable float
    return ((u64)fb << 32) | (u64)(0xFFFFFFFFu - j);
}

__device__ __forceinline__ float key_score(u64 k)
{
    unsigned fb = (unsigned)(k >> 32);
    unsigned orig = (fb & 0x80000000u) ? (fb ^ 0x80000000u) : ~fb;
    return __uint_as_float(orig);
}

// ---------------------------------------------------------------------------
// NMS: cluster of 8 CTAs per image; everything register-resident.
// ---------------------------------------------------------------------------
__global__ void __launch_bounds__(1024, 1) __cluster_dims__(CLU, 1, 1)
nms_kernel(float* __restrict__ out)
{
    __shared__ u64 keys[2][CLU];          // [parity][source rank]
    __shared__ u64 bcastB[2][CLU][2];     // winner box of each rank, 2x u64
    __shared__ u64 warpRed[32];
    __shared__ u64 ctaKeySh;
    __shared__ unsigned recIdx[NMS_ITERS];
    __shared__ float    recScore[NMS_ITERS];
    __shared__ int      slots[NMS_ITERS];

    const int t = threadIdx.x;
    uint32_t rank;
    asm("mov.u32 %0, %%cluster_ctarank;" : "=r"(rank));
    const int b = blockIdx.x >> 3;        // image
    const int base = b * M_ENT;
    const int lbase = (int)rank * PER_CTA;

    const uint32_t keysAddr  = smem_u32(&keys[0][0]);
    const uint32_t bcastAddr = smem_u32(&bcastB[0][0][0]);

    // load owned entries into registers
    float4 nb[PER_THR];
    float  s[PER_THR];
    float  area[PER_THR];
    #pragma unroll
    for (int e = 0; e < PER_THR; e++) {
        int j = lbase + e * 1024 + t;
        nb[e]   = g_nbox[base + j];
        s[e]    = g_s0[base + j];
        area[e] = (nb[e].z - nb[e].x) * (nb[e].w - nb[e].y);
    }

    for (int it = 0; it < NMS_ITERS; ++it) {
        const int p = it & 1;

        // 1. local argmax over 4 register entries
        u64 lmax = 0ull;
        #pragma unroll
        for (int e = 0; e < PER_THR; e++) {
            u64 k = pack_key(s[e], (unsigned)(lbase + e * 1024 + t));
            lmax = (k > lmax) ? k : lmax;
        }

        // 2. warp reduce
        u64 k = lmax;
        #pragma unroll
        for (int o = 16; o > 0; o >>= 1) {
            u64 other = __shfl_down_sync(0xffffffffu, k, o);
            k = (other > k) ? other : k;
        }
        if ((t & 31) == 0) warpRed[t >> 5] = k;
        __syncthreads();

        // 3. block reduce (warp 0) + multicast CTA key to all ranks
        if (t < 32) {
            k = warpRed[t];
            #pragma unroll
            for (int o = 16; o > 0; o >>= 1) {
                u64 other = __shfl_down_sync(0xffffffffu, k, o);
                k = (other > k) ? other : k;
            }
            k = __shfl_sync(0xffffffffu, k, 0);
            if (t == 0) ctaKeySh = k;
            if (t < CLU)
                st_cluster64(keysAddr + (uint32_t)(p * CLU + rank) * 8u, (uint32_t)t, k);
        }
        __syncthreads();

        // 4. CTA-winning thread multicasts its box to all ranks
        u64 ck = ctaKeySh;
        if (lmax == ck) {
            unsigned gi = 0xFFFFFFFFu - (unsigned)ck;
            int e = (int)((gi >> 10) & 3u);
            u64 v0 = ((u64)__float_as_uint(nb[e].y) << 32) | (u64)__float_as_uint(nb[e].x);
            u64 v1 = ((u64)__float_as_uint(nb[e].w) << 32) | (u64)__float_as_uint(nb[e].z);
            uint32_t slotA = bcastAddr + (uint32_t)((p * CLU + rank) * 2) * 8u;
            #pragma unroll
            for (uint32_t r = 0; r < CLU; r++) {
                st_cluster64(slotA,      r, v0);
                st_cluster64(slotA + 8u, r, v1);
            }
        }

        // 5. one cluster barrier per iteration (double-buffered slots)
        asm volatile("barrier.cluster.arrive.aligned;" ::: "memory");
        asm volatile("barrier.cluster.wait.aligned;"   ::: "memory");

        // 6. global winner = max over 8 CTA keys (broadcast smem reads)
        u64 wk = keys[p][0];
        #pragma unroll
        for (int r = 1; r < CLU; r++) {
            u64 o2 = keys[p][r];
            wk = (o2 > wk) ? o2 : wk;
        }
        unsigned gi = 0xFFFFFFFFu - (unsigned)wk;
        unsigned wr = gi >> 12;               // winning rank
        u64 b0 = bcastB[p][wr][0];
        u64 b1 = bcastB[p][wr][1];
        float sx = __uint_as_float((unsigned)(b0 & 0xFFFFFFFFu));
        float sy = __uint_as_float((unsigned)(b0 >> 32));
        float sz = __uint_as_float((unsigned)(b1 & 0xFFFFFFFFu));
        float sw = __uint_as_float((unsigned)(b1 >> 32));
        float a1 = (sz - sx) * (sw - sy);

        if (rank == 0 && t == 0) { recIdx[it] = gi; recScore[it] = key_score(wk); }

        // 7. suppress owned entries (registers only)
        #pragma unroll
        for (int e = 0; e < PER_THR; e++) {
            unsigned j = (unsigned)(lbase + e * 1024 + t);
            float ltx = fmaxf(sx, nb[e].x);
            float lty = fmaxf(sy, nb[e].y);
            float rbx = fminf(sz, nb[e].z);
            float rby = fminf(sw, nb[e].w);
            float iw = fmaxf(rbx - ltx, 0.0f);
            float ih = fmaxf(rby - lty, 0.0f);
            float inter = iw * ih;
            float iou = inter / (a1 + area[e] - inter);
            if (iou > 0.3f || j == gi) s[e] = NEGF;
        }
    }

    // ------------------- epilogue (rank-0 CTA of each image) ---------------
    __syncthreads();
    if (rank != 0) return;

    float* oBoxes  = out;                         // [8][320][4]
    float* oScores = out + BIMG * DET * 4;        // [8][320]
    float* oLabels = out + BIMG * DET * 5;        // [8][320]

    for (int q = t; q < DET * 4; q += 1024) oBoxes[b * DET * 4 + q] = 0.0f;
    for (int q = t; q < DET;     q += 1024) { oScores[b * DET + q] = 0.0f; oLabels[b * DET + q] = 0.0f; }

    if (t == 0) {
        int c0 = 0;
        for (int r = 0; r < NMS_ITERS; r++)
            if (recScore[r] > HALF_NEG && (recIdx[r] & 1u)) c0++;
        int p0 = 0, p1 = 0;
        for (int r = 0; r < NMS_ITERS; r++) {
            bool ok = recScore[r] > HALF_NEG;
            int slot = -1;
            if (ok) slot = (recIdx[r] & 1u) ? (p0++) : (c0 + p1++);
            slots[r] = slot;
        }
    }
    __syncthreads();

    if (t < NMS_ITERS) {
        int slot = slots[t];
        if (slot >= 0 && slot < DET) {
            unsigned i = recIdx[t];
            float4 bx = g_box[base + i];
            float* dst = oBoxes + (b * DET + slot) * 4;
            dst[0] = bx.x; dst[1] = bx.y; dst[2] = bx.z; dst[3] = bx.w;
            oScores[b * DET + slot] = recScore[t];
            oLabels[b * DET + slot] = (float)((i & 1u) + 1u);
        }
    }
}

// ---------------------------------------------------------------------------
extern "C" void kernel_launch(void* const* d_in, const int* in_sizes, int n_in,
                              void* d_out, int out_size)
{
    (void)in_sizes; (void)n_in; (void)out_size;
    const float* logits = (const float*)d_in[0];
    const float* breg   = (const float*)d_in[1];
    const float* props  = (const float*)d_in[2];
    float* out = (float*)d_out;

    prep_kernel<<<(BN + 255) / 256, 256>>>(logits, breg, props);
    nms_kernel<<<BIMG * CLU, 1024>>>(out);
}